// round 17
// baseline (speedup 1.0000x reference)
#include <cuda_runtime.h>
#include <cstdint>
#include <math.h>

#define HID 1024
#define KD  1024
#define NLEAF 8192
#define DEPTH 13

// k-permutation within each 8-float group: [k0,k4,k1,k5,k2,k6,k3,k7]
#define KPERM(k) (((k) & ~7) | (((k) & 3) << 1) | (((k) >> 2) & 1))

// Chunk-tiled GEMM operand layout: [r>>7][k>>5][r&127][32 floats], k-permuted and
// XOR-swizzled (u2 index ^ ((r&3)<<2)) so a linear 16KB bulk copy into smem yields
// conflict-free LDS.64 fragment loads.
__device__ __forceinline__ size_t tiled_off(int r, int k) {
    const int w = KPERM(k) & 31;
    const int physw = ((((w >> 1) ^ ((r & 3) << 2)) & 15) << 1) | (w & 1);
    return ((size_t)(r >> 7) * 32 + (k >> 5)) * 4096 + (size_t)((r & 127) * 32 + physw);
}

// ======================= device scratch =============================================
__device__ float g_h[2][NLEAF * HID];          // tiled layout (rows = nodes)
__device__ float g_c[2][NLEAF * HID];          // natural layout
__device__ float g_hs[(NLEAF / 2) * HID];      // tiled layout (rows = pairs)
__device__ float g_g3[(NLEAF / 2) * 3 * HID];  // natural
__device__ float g_gf[NLEAF * HID];            // natural
__device__ float g_wcat[4 * HID * KD];         // tiled, gate-interleaved rows 4*hh+g
__device__ float g_ucat3[3 * HID * KD];        // tiled
__device__ float g_uf[HID * KD];               // tiled
__device__ float g_tok[NLEAF * KD];            // tiled, PRE-GATHERED by leaf_ids
__device__ float g_opg[4 * 4 * HID];
__device__ float g_lc3[3 * HID];
__device__ float g_lf[2 * HID];

__device__ __forceinline__ float sigf(float x) { return 1.0f / (1.0f + expf(-x)); }

__device__ __forceinline__ uint32_t f2tf(float x) {
    uint32_t r;
    asm("cvt.rna.tf32.f32 %0, %1;" : "=r"(r) : "f"(x));
    return r;
}
__device__ __forceinline__ float f2tf_f(float x) { return __uint_as_float(f2tf(x)); }
__device__ __forceinline__ uint32_t smem_u32(const void* p) {
    uint32_t a;
    asm("{ .reg .u64 t; cvta.to.shared.u64 t, %1; cvt.u32.u64 %0, t; }" : "=r"(a) : "l"(p));
    return a;
}

// ---- mbarrier + bulk-copy primitives (sm_90 base PTX, no 'a' features) -------------
__device__ __forceinline__ void mbar_init(uint32_t mbar, uint32_t cnt) {
    asm volatile("mbarrier.init.shared.b64 [%0], %1;" :: "r"(mbar), "r"(cnt) : "memory");
}
__device__ __forceinline__ void mbar_expect(uint32_t mbar, uint32_t tx) {
    asm volatile("mbarrier.arrive.expect_tx.shared.b64 _, [%0], %1;"
                 :: "r"(mbar), "r"(tx) : "memory");
}
__device__ __forceinline__ void mbar_arrive(uint32_t mbar) {
    asm volatile("mbarrier.arrive.shared.b64 _, [%0];" :: "r"(mbar) : "memory");
}
__device__ __forceinline__ void mbar_wait(uint32_t mbar, uint32_t parity) {
    asm volatile(
        "{\n\t.reg .pred P;\n\t"
        "W%=:\n\t"
        "mbarrier.try_wait.parity.shared.b64 P, [%0], %1;\n\t"
        "@!P bra W%=;\n\t"
        "}\n\t" :: "r"(mbar), "r"(parity) : "memory");
}
__device__ __forceinline__ void bulk_cp16k(uint32_t dst, const float* src, uint32_t mbar) {
    asm volatile(
        "cp.async.bulk.shared::cta.global.mbarrier::complete_tx::bytes [%0], [%1], 16384, [%2];"
        :: "r"(dst), "l"(src), "r"(mbar) : "memory");
}

// ===== fused convert (tf32-round + tile) AND precompute (op table, leaf consts) =====
// blocks [0, 16*SEG/256): convert; blocks [16*SEG/256, +84): precompute.
__global__ void prep_kernel(
    const float* __restrict__ W_i, const float* __restrict__ W_o,
    const float* __restrict__ W_u, const float* __restrict__ W_f,
    const float* __restrict__ U_i, const float* __restrict__ U_o,
    const float* __restrict__ U_u, const float* __restrict__ U_f,
    const float* __restrict__ b_i, const float* __restrict__ b_o,
    const float* __restrict__ b_u, const float* __restrict__ b_f,
    const float* __restrict__ op_emb, const float* __restrict__ h_init,
    const float* __restrict__ tokens, const int* __restrict__ leaf_ids)
{
    const int SEG = (HID * KD) / 4;                       // 262144 float4
    const int CONV_BLOCKS = (16 * SEG) / 256;             // 16384
    if (blockIdx.x >= CONV_BLOCKS) {
        // ---- precompute path (exact fp32) ----
        int t = (blockIdx.x - CONV_BLOCKS) * 256 + threadIdx.x;
        if (t < 4 * 4 * HID) {
            int k = t >> 12; int rem = t & 4095; int g = rem >> 10; int hh = rem & 1023;
            const float* W = (g == 0) ? W_i : (g == 1) ? W_o : (g == 2) ? W_u : W_f;
            const float* b = (g == 0) ? b_i : (g == 1) ? b_o : (g == 2) ? b_u : b_f;
            const float* x = op_emb + k * KD;
            const float* w = W + (size_t)hh * KD;
            float acc = b[hh];
            for (int kk = 0; kk < KD; kk++) acc += x[kk] * w[kk];
            g_opg[t] = acc;
        } else if (t < 4 * 4 * HID + 3 * HID) {
            int t2 = t - 4 * 4 * HID; int g = t2 >> 10; int hh = t2 & 1023;
            const float* U = (g == 0) ? U_i : (g == 1) ? U_o : U_u;
            const float* b = (g == 0) ? b_i : (g == 1) ? b_o : b_u;
            const float* u = U + (size_t)hh * KD;
            float acc = b[hh];
            for (int kk = 0; kk < KD; kk++) acc += (h_init[kk] + h_init[KD + kk]) * u[kk];
            g_lc3[t2] = acc;
        } else if (t < 4 * 4 * HID + 3 * HID + 2 * HID) {
            int t2 = t - (4 * 4 * HID + 3 * HID); int ci = t2 >> 10; int hh = t2 & 1023;
            const float* u = U_f + (size_t)hh * KD;
            float acc = b_f[hh];
            for (int kk = 0; kk < KD; kk++) acc += h_init[ci * KD + kk] * u[kk];
            g_lf[t2] = acc;
        }
        return;
    }
    // ---- convert path ----
    int idx = blockIdx.x * 256 + threadIdx.x;             // < 16*SEG
    const float4* src;
    float* dstbase;
    int drow, k;
    if (idx < 4 * SEG) {                                  // Wcat -> row 4*hh+g
        int s = idx / SEG; size_t i = (size_t)(idx % SEG) * 4;
        src = (const float4*)(((s == 0) ? W_i : (s == 1) ? W_o : (s == 2) ? W_u : W_f) + i);
        dstbase = g_wcat; drow = 4 * (int)(i >> 10) + s; k = (int)(i & 1023);
    } else if (idx < 7 * SEG) {                           // U3 -> row s*1024+hh
        int s = (idx - 4 * SEG) / SEG; size_t i = (size_t)((idx - 4 * SEG) % SEG) * 4;
        src = (const float4*)(((s == 0) ? U_i : (s == 1) ? U_o : U_u) + i);
        dstbase = g_ucat3; drow = s * HID + (int)(i >> 10); k = (int)(i & 1023);
    } else if (idx < 8 * SEG) {                           // Uf
        size_t i = (size_t)(idx - 7 * SEG) * 4;
        src = (const float4*)(U_f + i);
        dstbase = g_uf; drow = (int)(i >> 10); k = (int)(i & 1023);
    } else {                                              // tokens, gathered by leaf
        size_t i = (size_t)(idx - 8 * SEG) * 4;
        drow = (int)(i >> 10); k = (int)(i & 1023);
        src = (const float4*)(tokens + (size_t)leaf_ids[drow] * KD + k);
        dstbase = g_tok;
    }
    float4 v = *src;
    dstbase[tiled_off(drow, k + 0)] = f2tf_f(v.x);
    dstbase[tiled_off(drow, k + 1)] = f2tf_f(v.y);
    dstbase[tiled_off(drow, k + 2)] = f2tf_f(v.z);
    dstbase[tiled_off(drow, k + 3)] = f2tf_f(v.w);
}

// ======================= bulk-fed tf32 mma GEMM core, 128x128 tile ==================
// 256 threads, 8 warps (4M x 2N) of 32x64 warptiles; 3-stage bulk pipeline with
// full (tx, cnt=1) + empty (cnt=8 warps) barriers — NO per-iter __syncthreads.
// smem per CTA: 3 x 32KB stages + barriers = 98368 B -> exactly 2 CTAs/SM.
static constexpr int GEMM_SMEM_BYTES = 3 * 32768 + 64;    // 98368

__device__ __forceinline__ void mma_tf32(float* c, uint32_t a0, uint32_t a1,
                                         uint32_t a2, uint32_t a3,
                                         uint32_t b0, uint32_t b1) {
    asm volatile(
        "mma.sync.aligned.m16n8k8.row.col.f32.tf32.tf32.f32 "
        "{%0,%1,%2,%3}, {%4,%5,%6,%7}, {%8,%9}, {%0,%1,%2,%3};"
        : "+f"(c[0]), "+f"(c[1]), "+f"(c[2]), "+f"(c[3])
        : "r"(a0), "r"(a1), "r"(a2), "r"(a3), "r"(b0), "r"(b1));
}

// Atiles/Btiles point at this CTA's [row-block] base: 32 chunks x 4096 floats each.
__device__ __forceinline__ void gemm_mainloop(
    const float* __restrict__ Atiles, const float* __restrict__ Btiles,
    float acc[2][8][4])
{
    extern __shared__ __align__(16) uint32_t sm[];
    const uint32_t smb = smem_u32(sm);
    const int tid = threadIdx.x;
    const uint32_t fullb  = smb + 98304;        // 3 x 8B
    const uint32_t emptyb = smb + 98304 + 24;   // 3 x 8B

    if (tid == 0) {
        #pragma unroll
        for (int s = 0; s < 3; s++) {
            mbar_init(fullb + s * 8, 1);
            mbar_init(emptyb + s * 8, 8);       // one arrive per warp
        }
    }
    __syncthreads();

    // producer step for chunk itp (tid 0 only)
    auto issue = [&](int itp) {
        const int s = itp % 3;
        if (itp >= 3) mbar_wait(emptyb + s * 8, ((itp / 3) & 1) ^ 1);
        const uint32_t mb = fullb + s * 8;
        mbar_expect(mb, 32768u);
        bulk_cp16k(smb + s * 32768,         Atiles + (size_t)itp * 4096, mb);
        bulk_cp16k(smb + s * 32768 + 16384, Btiles + (size_t)itp * 4096, mb);
    };

    const int wid  = tid >> 5;
    const int lane = tid & 31;
    const int wm  = (wid & 3) * 32;
    const int wn  = (wid >> 2) * 64;
    const int gid = lane >> 2;
    const int tig = lane & 3;
    const int sw  = (gid & 3) << 2;

    #pragma unroll
    for (int mi = 0; mi < 2; mi++)
        #pragma unroll
        for (int ni = 0; ni < 8; ni++)
            #pragma unroll
            for (int e = 0; e < 4; e++) acc[mi][ni][e] = 0.0f;

    auto compute = [&](int s) {
        const uint32_t* sa = sm + s * 8192;
        const uint32_t* sb = sa + 4096;
        #pragma unroll
        for (int kk = 0; kk < 32; kk += 8) {
            const int u2w = (((kk >> 1) + tig) ^ sw) << 1;
            uint2 a[2][2], b[8];
            #pragma unroll
            for (int mi = 0; mi < 2; mi++) {
                const uint32_t* ap = sa + (wm + mi * 16 + gid) * 32 + u2w;
                a[mi][0] = *(const uint2*)ap;
                a[mi][1] = *(const uint2*)(ap + 256);    // +8 rows
            }
            #pragma unroll
            for (int ni = 0; ni < 8; ni++)
                b[ni] = *(const uint2*)(sb + (wn + ni * 8 + gid) * 32 + u2w);
            #pragma unroll
            for (int mi = 0; mi < 2; mi++)
                #pragma unroll
                for (int ni = 0; ni < 8; ni++)
                    mma_tf32(acc[mi][ni],
                             a[mi][0].x, a[mi][1].x, a[mi][0].y, a[mi][1].y,
                             b[ni].x, b[ni].y);
        }
    };

    if (tid == 0) { issue(0); issue(1); }
    #pragma unroll 1
    for (int it = 0; it < 32; it++) {
        const int s = it % 3;
        if (tid == 0 && it + 2 < 32) issue(it + 2);   // refill gated by empty barrier
        mbar_wait(fullb + s * 8, (uint32_t)((it / 3) & 1));
        compute(s);
        if (lane == 0) mbar_arrive(emptyb + s * 8);
    }
}

// ---- leaf GEMM with fused gate epilogue (Wcat cols n = 4*hh+g) ---------------------
__global__ void __launch_bounds__(256, 2)
leaf_gemm_fused(const float* __restrict__ c_init,
                float* __restrict__ c_out, float* __restrict__ h_out,
                float* __restrict__ hs_out,
                const float* __restrict__ Atok, const float* __restrict__ Bw)
{
    const int m0 = blockIdx.y * 128;
    const int n0 = blockIdx.x * 128;
    float acc[2][8][4];
    gemm_mainloop(Atok + (size_t)(m0 >> 7) * 131072,
                  Bw   + (size_t)(n0 >> 7) * 131072, acc);

    const int wid  = threadIdx.x >> 5;
    const int lane = threadIdx.x & 31;
    const int wm  = (wid & 3) * 32;
    const int wn  = (wid >> 2) * 64;
    const int gid = lane >> 2;
    const int tig = lane & 3;
    const int pbit = tig & 1;           // 0: holds (i,o) preacts; 1: holds (u,f)

    #pragma unroll
    for (int ni = 0; ni < 8; ni++) {
        const int hh = ((n0 + wn) >> 2) + ni * 2 + (tig >> 1);
        const float lci = g_lc3[hh], lco = g_lc3[HID + hh], lcu = g_lc3[2 * HID + hh];
        const float lf0 = g_lf[hh],  lf1 = g_lf[HID + hh];
        const float ci0 = c_init[hh], ci1 = c_init[HID + hh];
        #pragma unroll
        for (int mi = 0; mi < 2; mi++) {
            #pragma unroll
            for (int half = 0; half < 2; half++) {
                const int r = m0 + wm + mi * 16 + gid + half * 8;
                const float x0 = acc[mi][ni][half * 2 + 0];
                const float x1 = acc[mi][ni][half * 2 + 1];
                const float p0 = __shfl_xor_sync(0xFFFFFFFFu, x0, 1);
                const float p1 = __shfl_xor_sync(0xFFFFFFFFu, x1, 1);
                const float gi = sigf(x0 + lci);
                const float go = sigf(x1 + lco);
                const float gu = tanhf(p0 + lcu);
                const float xf = p1;
                const float c = gi * gu + sigf(xf + lf0) * ci0 + sigf(xf + lf1) * ci1;
                const float h = go * tanhf(c);
                const float hsib = __shfl_xor_sync(0xFFFFFFFFu, h, 4);  // sibling leaf
                if (pbit == 0) {
                    c_out[(size_t)r * HID + hh] = c;
                    h_out[tiled_off(r, hh)] = f2tf_f(h);
                    if ((gid & 1) == 0)
                        hs_out[tiled_off(r >> 1, hh)] = f2tf_f(h + hsib);
                }
            }
        }
    }
}

// ---- merged per-level GEMM: bx<24 -> G3 (hs@U3^T), bx>=24 -> Gf (h@Uf^T) -----------
__global__ void __launch_bounds__(256, 2)
level_gemm(const float* __restrict__ hs, const float* __restrict__ h,
           const float* __restrict__ U3, const float* __restrict__ Uf,
           float* __restrict__ g3, float* __restrict__ gf, int m)
{
    const int bx = blockIdx.x;
    const int m0 = blockIdx.y * 128;
    const float* A;
    const float* B;
    float* C;
    int M, N, n0;
    if (bx < 24) {
        if (m0 >= m) return;
        A = hs; B = U3; C = g3; M = m; N = 3 * HID; n0 = bx * 128;
    } else {
        if (m0 >= 2 * m) return;
        A = h; B = Uf; C = gf; M = 2 * m; N = HID; n0 = (bx - 24) * 128;
    }
    float acc[2][8][4];
    gemm_mainloop(A + (size_t)(m0 >> 7) * 131072,
                  B + (size_t)(n0 >> 7) * 131072, acc);

    const int wid  = threadIdx.x >> 5;
    const int lane = threadIdx.x & 31;
    const int wm  = (wid & 3) * 32;
    const int wn  = (wid >> 2) * 64;
    const int gid = lane >> 2;
    const int tig = lane & 3;
    #pragma unroll
    for (int mi = 0; mi < 2; mi++) {
        const int r0 = m0 + wm + mi * 16 + gid;
        #pragma unroll
        for (int ni = 0; ni < 8; ni++) {
            const int col = n0 + wn + ni * 8 + tig * 2;
            if (r0 < M)
                *(float2*)(C + (size_t)r0 * N + col) = make_float2(acc[mi][ni][0], acc[mi][ni][1]);
            if (r0 + 8 < M)
                *(float2*)(C + (size_t)(r0 + 8) * N + col) = make_float2(acc[mi][ni][2], acc[mi][ni][3]);
        }
    }
}

// ========== node gate epilogues (pair-fused; h & hs tf32-rounded, tiled) ============
__global__ void node_gate_pair_kernel(int m, int off, const int* __restrict__ op_ids,
                                      const float* __restrict__ c_in,
                                      float* __restrict__ c_out, float* __restrict__ h_out,
                                      float* __restrict__ hs_out)
{
    int idx = blockIdx.x * blockDim.x + threadIdx.x;
    if (idx >= (m >> 1) * HID) return;
    int hh = idx & 1023;
    int p = idx >> 10;
    float hsum = 0.0f;
    #pragma unroll
    for (int s = 0; s < 2; s++) {
        const int j = 2 * p + s;
        const float* og = g_opg + op_ids[off + j] * 4 * HID;
        const float* g3 = g_g3 + (size_t)j * 3 * HID;
        float i = sigf(og[hh]            + g3[hh]);
        float o = sigf(og[HID + hh]      + g3[HID + hh]);
        float u = tanhf(og[2 * HID + hh] + g3[2 * HID + hh]);
        float xf = og[3 * HID + hh];
        float f0 = sigf(xf + g_gf[(size_t)(2 * j) * HID + hh]);
        float f1 = sigf(xf + g_gf[(size_t)(2 * j + 1) * HID + hh]);
        float c = i * u + f0 * c_in[(size_t)(2 * j) * HID + hh]
                        + f1 * c_in[(size_t)(2 * j + 1) * HID + hh];
        float h = o * tanhf(c);
        c_out[(size_t)j * HID + hh] = c;
        h_out[tiled_off(j, hh)] = f2tf_f(h);
        hsum += h;
    }
    hs_out[tiled_off(p, hh)] = f2tf_f(hsum);
}

__global__ void node_gate_root_kernel(const int* __restrict__ op_ids,
                                      const float* __restrict__ c_in,
                                      float* __restrict__ c_out, float* __restrict__ h_out)
{
    int hh = blockIdx.x * blockDim.x + threadIdx.x;
    if (hh >= HID) return;
    const float* og = g_opg + op_ids[0] * 4 * HID;
    float i = sigf(og[hh]            + g_g3[hh]);
    float o = sigf(og[HID + hh]      + g_g3[HID + hh]);
    float u = tanhf(og[2 * HID + hh] + g_g3[2 * HID + hh]);
    float xf = og[3 * HID + hh];
    float f0 = sigf(xf + g_gf[hh]);
    float f1 = sigf(xf + g_gf[HID + hh]);
    float c = i * u + f0 * c_in[hh] + f1 * c_in[HID + hh];
    c_out[hh] = c;
    h_out[hh] = o * tanhf(c);
}

// ======================= host launch ================================================
extern "C" void kernel_launch(void* const* d_in, const int* in_sizes, int n_in,
                              void* d_out, int out_size)
{
    const float* tokens   = (const float*)d_in[0];
    const int*   leaf_ids = (const int*)  d_in[1];
    const int*   op_ids   = (const int*)  d_in[2];
    const float* W_i = (const float*)d_in[3];
    const float* W_o = (const float*)d_in[4];
    const float* W_u = (const float*)d_in[5];
    const float* W_f = (const float*)d_in[6];
    const float* U_i = (const float*)d_in[7];
    const float* U_o = (const float*)d_in[8];
    const float* U_u = (const float*)d_in[9];
    const float* U_f = (const float*)d_in[10];
    const float* b_i = (const float*)d_in[11];
    const float* b_o = (const float*)d_in[12];
    const float* b_u = (const float*)d_in[13];
    const float* b_f = (const float*)d_in[14];
    const float* op_emb = (const float*)d_in[15];
    const float* c_init = (const float*)d_in[16];
    const float* h_init = (const float*)d_in[17];
    float* out = (float*)d_out;

    cudaFuncSetAttribute(leaf_gemm_fused, cudaFuncAttributeMaxDynamicSharedMemorySize, GEMM_SMEM_BYTES);
    cudaFuncSetAttribute(level_gemm,      cudaFuncAttributeMaxDynamicSharedMemorySize, GEMM_SMEM_BYTES);

    void* p;
    cudaGetSymbolAddress(&p, g_h);     float* hbase = (float*)p;
    cudaGetSymbolAddress(&p, g_c);     float* cbase = (float*)p;
    cudaGetSymbolAddress(&p, g_hs);    float* hsp   = (float*)p;
    cudaGetSymbolAddress(&p, g_g3);    float* g3p   = (float*)p;
    cudaGetSymbolAddress(&p, g_gf);    float* gfp   = (float*)p;
    cudaGetSymbolAddress(&p, g_wcat);  float* wcat  = (float*)p;
    cudaGetSymbolAddress(&p, g_ucat3); float* ucat3 = (float*)p;
    cudaGetSymbolAddress(&p, g_uf);    float* ufp   = (float*)p;
    cudaGetSymbolAddress(&p, g_tok);   float* tokp  = (float*)p;

    float* hbuf[2] = { hbase, hbase + (size_t)NLEAF * HID };
    float* cbuf[2] = { cbase, cbase + (size_t)NLEAF * HID };

    // fused convert + precompute (one launch; independent block families)
    prep_kernel<<<(16 * (HID * KD / 4)) / 256 + 84, 256>>>(
        W_i, W_o, W_u, W_f, U_i, U_o, U_u, U_f,
        b_i, b_o, b_u, b_f, op_emb, h_init, tokens, leaf_ids);

    // Leaf level: GEMM + gates fused (M=8192, N=4096 gate-interleaved)
    leaf_gemm_fused<<<dim3(32, 64), 256, GEMM_SMEM_BYTES>>>(
        c_init, cbuf[0], hbuf[0], hsp, tokp, wcat);

    int cur = 0;
    for (int l = DEPTH - 1; l >= 0; l--) {
        const int m = 1 << l;
        const int off = m - 1;
        const int nxt = cur ^ 1;
        level_gemm<<<dim3(32, (2 * m + 127) / 128), 256, GEMM_SMEM_BYTES>>>(
            hsp, hbuf[cur], ucat3, ufp, g3p, gfp, m);
        if (m > 1) {
            node_gate_pair_kernel<<<((m / 2) * HID + 255) / 256, 256>>>(
                m, off, op_ids, cbuf[cur], cbuf[nxt], hbuf[nxt], hsp);
        } else {
            node_gate_root_kernel<<<4, 256>>>(op_ids, cbuf[cur], cbuf[nxt], hbuf[nxt]);
        }
        cur = nxt;
    }

    cudaMemcpyAsync(out,       cbuf[cur], HID * sizeof(float), cudaMemcpyDeviceToDevice, 0);
    cudaMemcpyAsync(out + HID, hbuf[cur], HID * sizeof(float), cudaMemcpyDeviceToDevice, 0);
}